// round 7
// baseline (speedup 1.0000x reference)
#include <cuda_runtime.h>
#include <cstdint>

// Problem constants
#define S        1048576              // 1024*1024
#define S4       (S / 4)
#define TPB      256
#define NSLAB    10                   // TT0:r0, TT1:r0..2, TT2:r0..2, TT3:r0..2
#define PBLK     256                  // blocks per slab
#define RBLK     (NSLAB * PBLK)       // 2560 blocks
#define SPB      (S / PBLK)           // 4096 s-values per block
#define CHUNK_S  1024                 // s-values per pipeline chunk
#define NCHUNK   (SPB / CHUNK_S)      // 4 chunks per block
#define Z_BYTES  (CHUNK_S * 4)        // 4096
#define SL_BYTES (CHUNK_S * 12)       // 12288 (3 floats per s)
#define DSMEM    (NCHUNK * (Z_BYTES + SL_BYTES))   // 65536 bytes
#define NCOMP    30                   // 10 slabs x 3 q-components
#define CBLK     256                  // bcast blocks

// Deterministic scratch (no device allocation allowed)
__device__ float        g_bpart[NCOMP * PBLK];   // [comp][PBLK]
__device__ float        g_f[3];
__device__ unsigned int g_ctr = 0;               // reset by last block

// ---- tiny PTX helpers -----------------------------------------------------
__device__ __forceinline__ uint32_t smem_u32(const void* p) {
    uint32_t a;
    asm("{ .reg .u64 t; cvta.to.shared.u64 t, %1; cvt.u32.u64 %0, t; }"
        : "=r"(a) : "l"(p));
    return a;
}
__device__ __forceinline__ void mbar_init(uint32_t mbar, uint32_t cnt) {
    asm volatile("mbarrier.init.shared.b64 [%0], %1;" :: "r"(mbar), "r"(cnt) : "memory");
}
__device__ __forceinline__ void mbar_expect_tx(uint32_t mbar, uint32_t bytes) {
    asm volatile("mbarrier.arrive.expect_tx.shared.b64 _, [%0], %1;"
                 :: "r"(mbar), "r"(bytes) : "memory");
}
__device__ __forceinline__ void bulk_g2s(uint32_t dst, const void* src,
                                         uint32_t bytes, uint32_t mbar) {
    asm volatile("cp.async.bulk.shared::cta.global.mbarrier::complete_tx::bytes "
                 "[%0], [%1], %2, [%3];"
                 :: "r"(dst), "l"(src), "r"(bytes), "r"(mbar) : "memory");
}
__device__ __forceinline__ void mbar_wait(uint32_t mbar, uint32_t parity) {
    uint32_t done;
    asm volatile("{ .reg .pred p; "
                 "mbarrier.try_wait.parity.acquire.cta.shared::cta.b64 p, [%1], %2; "
                 "selp.b32 %0, 1, 0, p; }"
                 : "=r"(done) : "r"(mbar), "r"(parity) : "memory");
    if (!done) {
        asm volatile("{ .reg .pred P1; "
                     "WL%=: mbarrier.try_wait.parity.acquire.cta.shared::cta.b64 P1, [%0], %1, 0x989680; "
                     "@P1 bra.uni WD%=; bra.uni WL%=; WD%=: }"
                     :: "r"(mbar), "r"(parity) : "memory");
    }
}

// ---------------------------------------------------------------------------
// Kernel A: TMA-fed slab reduction + fused finalize.
//   slab = bid % NSLAB  (same-s-range blocks co-scheduled -> z dedups in L2)
// Dynamic smem layout (floats):
//   [0           .. NCHUNK*1024)           z chunks
//   [NCHUNK*1024 .. NCHUNK*1024+NCHUNK*3072) slab chunks
// ---------------------------------------------------------------------------
__global__ void __launch_bounds__(TPB, 2)
reduce_k(const float* __restrict__ z,
         const float* __restrict__ t0,
         const float* __restrict__ t1,
         const float* __restrict__ t2,
         const float* __restrict__ t3) {
    extern __shared__ float smem[];
    __shared__ alignas(8) uint64_t bar[NCHUNK];
    __shared__ float sred[TPB / 32][3];

    const int slab = blockIdx.x % NSLAB;
    const int blk  = blockIdx.x / NSLAB;

    const float* base;
    {
        const int r = (slab == 0) ? 0 : ((slab - 1) % 3);
        const float* t = (slab == 0) ? t0 : (slab <= 3 ? t1 : (slab <= 6 ? t2 : t3));
        base = t + (size_t)r * (3u * S);
    }

    const uint32_t smem_b = smem_u32(smem);
    const uint32_t bar_b  = smem_u32(bar);

    if (threadIdx.x == 0) {
#pragma unroll
        for (int c = 0; c < NCHUNK; c++) mbar_init(bar_b + c * 8, 1);
    }
    __syncthreads();

    if (threadIdx.x == 0) {
        const int s0 = blk * SPB;                      // block's first s
#pragma unroll
        for (int c = 0; c < NCHUNK; c++) {
            const int sc = s0 + c * CHUNK_S;
            mbar_expect_tx(bar_b + c * 8, Z_BYTES + SL_BYTES);
            bulk_g2s(smem_b + c * Z_BYTES, z + sc, Z_BYTES, bar_b + c * 8);
            bulk_g2s(smem_b + NCHUNK * Z_BYTES + c * SL_BYTES,
                     base + (size_t)sc * 3, SL_BYTES, bar_b + c * 8);
        }
    }

    float a0 = 0.0f, a1 = 0.0f, a2 = 0.0f;

#pragma unroll
    for (int c = 0; c < NCHUNK; c++) {
        mbar_wait(bar_b + c * 8, 0);
        // thread t: s-range [t*4, t*4+4) of this chunk
        const float4* zp = reinterpret_cast<const float4*>(smem + c * CHUNK_S) + threadIdx.x;
        const float4* sp = reinterpret_cast<const float4*>(smem + NCHUNK * CHUNK_S + c * CHUNK_S * 3)
                           + threadIdx.x * 3;
        float4 zv = zp[0];
        float4 v0 = sp[0];
        float4 v1 = sp[1];
        float4 v2 = sp[2];
        // 12 consecutive floats = 4 s x 3 q ; elem e -> (s=e/3, q=e%3)
        a0 += zv.x * v0.x;  a1 += zv.x * v0.y;  a2 += zv.x * v0.z;
        a0 += zv.y * v0.w;  a1 += zv.y * v1.x;  a2 += zv.y * v1.y;
        a0 += zv.z * v1.z;  a1 += zv.z * v1.w;  a2 += zv.z * v2.x;
        a0 += zv.w * v2.y;  a1 += zv.w * v2.z;  a2 += zv.w * v2.w;
    }

    // Warp + block reduction of 3 components
    const unsigned FULL = 0xffffffffu;
#pragma unroll
    for (int off = 16; off >= 1; off >>= 1) {
        a0 += __shfl_down_sync(FULL, a0, off);
        a1 += __shfl_down_sync(FULL, a1, off);
        a2 += __shfl_down_sync(FULL, a2, off);
    }
    const int warp = threadIdx.x >> 5;
    const int lane = threadIdx.x & 31;
    if (lane == 0) { sred[warp][0] = a0; sred[warp][1] = a1; sred[warp][2] = a2; }
    __syncthreads();

    if (threadIdx.x < 3) {
        float s = 0.0f;
#pragma unroll
        for (int w = 0; w < TPB / 32; w++) s += sred[w][threadIdx.x];
        g_bpart[(slab * 3 + threadIdx.x) * PBLK + blk] = s;   // deterministic
    }

    // ---- last block: finalize f = V0 @ V1 @ V2 @ V3 ----
    __shared__ bool amLast;
    __threadfence();
    if (threadIdx.x == 0)
        amLast = (atomicAdd(&g_ctr, 1u) == (unsigned)(RBLK - 1));
    __syncthreads();

    if (amLast) {
        __threadfence();                         // see all blocks' partials
        __shared__ float sV[NCOMP][8];
        const int comp = threadIdx.x >> 3;       // 0..31 (use 0..29)
        const int part = threadIdx.x & 7;        // 8 parts x 32 partials
        if (comp < NCOMP) {
            const float4* pp =
                reinterpret_cast<const float4*>(g_bpart + comp * PBLK) + part * 8;
            float s = 0.0f;
#pragma unroll
            for (int j = 0; j < 8; j++) { float4 v = pp[j]; s += v.x + v.y + v.z + v.w; }
            sV[comp][part] = s;
        }
        __syncthreads();

        if (threadIdx.x == 0) {
            float V[NCOMP];
#pragma unroll
            for (int i = 0; i < NCOMP; i++) {
                float s = 0.0f;
#pragma unroll
                for (int j = 0; j < 8; j++) s += sV[i][j];
                V[i] = s;
            }
            float f0 = V[0], f1 = V[1], f2 = V[2];        // V0 : (1,3)
#pragma unroll
            for (int cc = 0; cc < 3; cc++) {              // V1,V2,V3 (3x3 [r*3+q])
                const float* M = V + 3 + cc * 9;
                float g0 = f0 * M[0] + f1 * M[3] + f2 * M[6];
                float g1 = f0 * M[1] + f1 * M[4] + f2 * M[7];
                float g2 = f0 * M[2] + f1 * M[5] + f2 * M[8];
                f0 = g0; f1 = g1; f2 = g2;
            }
            g_f[0] = f0; g_f[1] = f1; g_f[2] = f2;
            g_ctr = 0;                            // reset for next replay
        }
    }
}

// ---------------------------------------------------------------------------
// Kernel C: out[s] = f0*TT4[0,s,0] + f1*TT4[1,s,0] + f2*TT4[2,s,0]
// 4 chunks per thread, loads batched for MLP (fixes latency-bound 2.5 TB/s).
// ---------------------------------------------------------------------------
__global__ void __launch_bounds__(TPB)
bcast_k(const float* __restrict__ t4, float* __restrict__ out) {
    const float f0 = g_f[0];
    const float f1 = g_f[1];
    const float f2 = g_f[2];

    const float4* p = reinterpret_cast<const float4*>(t4);
    float4 a[4], b[4], c[4];
    int idx[4];
#pragma unroll
    for (int j = 0; j < 4; j++) {
        idx[j] = blockIdx.x * TPB + threadIdx.x + j * (CBLK * TPB);
        a[j] = p[idx[j]];
        b[j] = p[S4 + idx[j]];
        c[j] = p[2 * S4 + idx[j]];
    }
#pragma unroll
    for (int j = 0; j < 4; j++) {
        float4 o;
        o.x = f0 * a[j].x + f1 * b[j].x + f2 * c[j].x;
        o.y = f0 * a[j].y + f1 * b[j].y + f2 * c[j].y;
        o.z = f0 * a[j].z + f1 * b[j].z + f2 * c[j].z;
        o.w = f0 * a[j].w + f1 * b[j].w + f2 * c[j].w;
        reinterpret_cast<float4*>(out)[idx[j]] = o;
    }
}

// ---------------------------------------------------------------------------
extern "C" void kernel_launch(void* const* d_in, const int* in_sizes, int n_in,
                              void* d_out, int out_size) {
    const float* z  = (const float*)d_in[0];
    const float* t0 = (const float*)d_in[1];
    const float* t1 = (const float*)d_in[2];
    const float* t2 = (const float*)d_in[3];
    const float* t3 = (const float*)d_in[4];
    const float* t4 = (const float*)d_in[5];
    float* out = (float*)d_out;

    cudaFuncSetAttribute(reduce_k, cudaFuncAttributeMaxDynamicSharedMemorySize, DSMEM);

    reduce_k<<<RBLK, TPB, DSMEM>>>(z, t0, t1, t2, t3);
    bcast_k<<<CBLK, TPB>>>(t4, out);
}